// round 2
// baseline (speedup 1.0000x reference)
#include <cuda_runtime.h>

#define LAYERS   8
#define WIDTH    128
#define DDIM     64
#define KNOTS    8
#define PPD      23          // 3*KNOTS-1
#define BATCH    16384
#define TB       64          // batch rows per CTA
#define NTHREADS 256
#define DG       4           // dims per chunk
#define NCHUNK   (DDIM/DG)   // 16
#define WSROWS   (DG*PPD)    // 92
#define WSPAD    68          // padded row stride (floats): conflict-free, 16B-aligned
#define XPAD     68          // X row stride (floats)
#define HPAD     132         // H row stride (floats)
#define BI       4.0f

// shared memory layout (float offsets)
#define OFF_X0   0
#define OFF_X1   (TB*XPAD)                   // 4352
#define OFF_H    (2*TB*XPAD)                 // 8704
#define OFF_WS   (2*TB*XPAD + TB*HPAD)       // 17152
#define SMEM_FLOATS (OFF_WS + WIDTH*WSPAD)   // 17152 + 8704 = 25856
#define SMEM_BYTES  (SMEM_FLOATS*4)          // 103424 B -> 2 CTAs/SM

// Pre-masked weights (static device scratch)
__device__ float g_W1m[2*LAYERS*WIDTH*DDIM];
__device__ float g_Wom[2*LAYERS*DDIM*PPD*WIDTH];

// ---------------------------------------------------------------------------
// packed fp32x2 FMA (sm_103a): 2 MACs per issue slot on the fma pipe
// ---------------------------------------------------------------------------
__device__ __forceinline__ unsigned long long ffma2(unsigned long long a,
                                                    unsigned long long b,
                                                    unsigned long long c)
{
    unsigned long long d;
    asm("fma.rn.f32x2 %0, %1, %2, %3;" : "=l"(d) : "l"(a), "l"(b), "l"(c));
    return d;
}
__device__ __forceinline__ float2 unpack2(unsigned long long v)
{
    float2 r;
    asm("mov.b64 {%0, %1}, %2;" : "=f"(r.x), "=f"(r.y) : "l"(v));
    return r;
}

// ---------------------------------------------------------------------------
// Prep: apply MADE masks to W1 and Wout once per launch.
// ---------------------------------------------------------------------------
__global__ void prep_kernel(const float* __restrict__ fW1, const float* __restrict__ fWo,
                            const float* __restrict__ gW1, const float* __restrict__ gWo)
{
    const int N1 = LAYERS*WIDTH*DDIM;
    const int N2 = LAYERS*DDIM*PPD*WIDTH;
    const int stride = gridDim.x * blockDim.x;
    for (int i = blockIdx.x*blockDim.x + threadIdx.x; i < 2*N1; i += stride) {
        int fl = i / N1, j = i - fl*N1;
        int w = (j >> 6) & (WIDTH-1);
        int c = j & (DDIM-1);
        const float* s = fl ? gW1 : fW1;
        g_W1m[i] = (c <= (w % (DDIM-1))) ? s[j] : 0.f;
    }
    for (int i = blockIdx.x*blockDim.x + threadIdx.x; i < 2*N2; i += stride) {
        int fl = i / N2, j = i - fl*N2;
        int w = j & (WIDTH-1);
        int o = (j >> 7) % (DDIM*PPD);
        int d = o / PPD;
        const float* s = fl ? gWo : fWo;
        g_Wom[i] = ((w % (DDIM-1)) < d) ? s[j] : 0.f;
    }
}

// ---------------------------------------------------------------------------
// Rational-quadratic spline (fully unrolled, register-resident)
// ---------------------------------------------------------------------------
__device__ __forceinline__ void rqs_eval(const float par[PPD], float xraw,
                                         float& xout, float& ldj)
{
    const float C1 = 8.0f / 1.01f;
    const float CADJ = 0.00125f;

    float mw = par[0];
#pragma unroll
    for (int j = 1; j < 8; j++) mw = fmaxf(mw, par[j]);
    float ew[8]; float sw = 0.f;
#pragma unroll
    for (int j = 0; j < 8; j++) { ew[j] = __expf(par[j] - mw); sw += ew[j]; }
    float isw = __frcp_rn(sw);

    float mh = par[8];
#pragma unroll
    for (int j = 1; j < 8; j++) mh = fmaxf(mh, par[8+j]);
    float eh[8]; float sh = 0.f;
#pragma unroll
    for (int j = 0; j < 8; j++) { eh[j] = __expf(par[8+j] - mh); sh += eh[j]; }
    float ish = __frcp_rn(sh);

    float sd[7];
#pragma unroll
    for (int j = 0; j < 7; j++) {
        float v = par[16+j];
        float sp = (v > 15.f) ? v : log1pf(__expf(v));
        sd[j] = sp + 0.001f;
    }

    float xc = fminf(fmaxf(xraw, -BI), BI);

    float xl = -BI, yl = -BI;
    float xk = 0.f, xk1 = 1.f, yk = 0.f, yk1 = 1.f, dk = 1.f, dk1 = 1.f;
    bool found = false;
#pragma unroll
    for (int j = 0; j < 8; j++) {
        float wj = (ew[j]*isw + CADJ) * C1;
        float hj = (eh[j]*ish + CADJ) * C1;
        float xr2 = xl + wj;
        float yr2 = yl + hj;
        bool sel = (!found) && ((xc < xr2) || (j == 7));
        if (sel) {
            xk = xl; xk1 = xr2; yk = yl; yk1 = yr2;
            dk  = (j == 0) ? 1.f : sd[j-1];
            dk1 = (j == 7) ? 1.f : sd[j];
            found = true;
        }
        xl = xr2; yl = yr2;
    }

    float invdx = __frcp_rn(xk1 - xk);
    float dyv = yk1 - yk;
    float sk  = dyv * invdx;
    float xi  = (xc - xk) * invdx;
    float omx = 1.f - xi;
    float xiomx = xi * omx;
    float den = sk + (dk1 + dk - 2.f*sk) * xiomx;
    float invden = __frcp_rn(den);
    float nume = sk*xi*xi + dk*xiomx;
    float outv = yk + dyv * nume * invden;
    float ldn = dk1*xi*xi + 2.f*sk*xiomx + dk*omx*omx;
    float ld = 2.f*__logf(sk) + __logf(ldn) - 2.f*__logf(den);

    bool inside = (xraw > -BI) && (xraw < BI);
    xout = inside ? outv : xraw;
    ldj  = inside ? ld : 0.f;
}

// ---------------------------------------------------------------------------
// Main kernel: one CTA processes TB=64 rows through all 8 layers.
// 2 CTAs/SM; GEMMs in packed fp32x2.
// ---------------------------------------------------------------------------
__global__ __launch_bounds__(NTHREADS, 2)
void maf_kernel(const float* __restrict__ xin_f, const float* __restrict__ xin_g,
                const float* __restrict__ f_b1, const float* __restrict__ f_bout,
                const float* __restrict__ g_b1, const float* __restrict__ g_bout,
                float* __restrict__ out)
{
    extern __shared__ float sm[];
    const int tid  = threadIdx.x;
    const int flow = blockIdx.y;
    const int row0 = blockIdx.x * TB;

    const float* xin   = flow ? xin_g  : xin_f;
    const float* b1g   = flow ? g_b1   : f_b1;
    const float* boutg = flow ? g_bout : f_bout;
    const float* W1m   = g_W1m + flow * (LAYERS*WIDTH*DDIM);
    const float* Wom   = g_Wom + flow * (LAYERS*DDIM*PPD*WIDTH);

    // load batch tile into padded X
    for (int i = tid; i < TB*DDIM; i += NTHREADS) {
        int r = i >> 6, d = i & 63;
        sm[OFF_X0 + r*XPAD + d] = xin[row0*DDIM + i];
    }

    const int dl = tid & (DG-1);   // dim-local within chunk (0..3)
    const int r  = tid >> 2;       // this thread's batch row (0..63)

    float ldacc = 0.f;
    int cur = OFF_X0, nxt = OFF_X1;

    __syncthreads();

    for (int layer = 0; layer < LAYERS; layer++) {
        // ---- stage masked W1 into WS area, layout [w][WSPAD]
        const float* W1l = W1m + layer*WIDTH*DDIM;
        for (int i = tid; i < WIDTH*DDIM/4; i += NTHREADS) {
            int w = i >> 4, c4 = i & 15;
            float4 v = ((const float4*)W1l)[i];
            *(float4*)&sm[OFF_WS + w*WSPAD + c4*4] = v;
        }
        __syncthreads();

        // ---- GEMM1: H = relu(X @ W1m^T + b1), packed over k
        for (int it = 0; it < (TB*WIDTH)/NTHREADS; it++) {
            int idx = tid + it*NTHREADS;
            int rr = idx >> 7, w = idx & (WIDTH-1);
            const float* xr = &sm[cur + rr*XPAD];
            const float* wr = &sm[OFF_WS + w*WSPAD];
            unsigned long long a2 = 0ull;
#pragma unroll
            for (int iv = 0; iv < 16; iv++) {
                ulonglong2 xv = *(const ulonglong2*)&xr[iv*4];
                ulonglong2 wv = *(const ulonglong2*)&wr[iv*4];
                a2 = ffma2(xv.x, wv.x, a2);
                a2 = ffma2(xv.y, wv.y, a2);
            }
            float2 p2 = unpack2(a2);
            float a = p2.x + p2.y + b1g[layer*WIDTH + w];
            sm[OFF_H + rr*HPAD + w] = fmaxf(a, 0.f);
        }
        __syncthreads();

        // ---- GEMM2 + spline, chunked over dims (4 dims per chunk)
        for (int chunk = 0; chunk < NCHUNK; chunk++) {
            const int d0 = chunk * DG;
            const int d  = d0 + dl;

            unsigned long long acc[PPD];
#pragma unroll
            for (int p = 0; p < PPD; p++) acc[p] = 0ull;

            const float* Wol = Wom + (layer*DDIM*PPD + d0*PPD) * WIDTH;

            for (int kh = 0; kh < 2; kh++) {
                // stage WS: 92 rows x 64 cols of Wout (this k-half)
                for (int i = tid; i < WSROWS*16; i += NTHREADS) {
                    int rr = i >> 4, c4 = i & 15;
                    float4 v = *(const float4*)&Wol[rr*WIDTH + kh*64 + c4*4];
                    *(float4*)&sm[OFF_WS + rr*WSPAD + c4*4] = v;
                }
                __syncthreads();

                const float* hsrc = &sm[OFF_H + r*HPAD + kh*64];
                const float* wsp  = &sm[OFF_WS + dl*PPD*WSPAD];

                for (int k4 = 0; k4 < 16; k4++) {
                    ulonglong2 hv = *(const ulonglong2*)&hsrc[k4*4];
#pragma unroll
                    for (int p = 0; p < PPD; p++) {
                        ulonglong2 wv = *(const ulonglong2*)&wsp[p*WSPAD + k4*4];
                        acc[p] = ffma2(hv.x, wv.x, acc[p]);
                        acc[p] = ffma2(hv.y, wv.y, acc[p]);
                    }
                }
                __syncthreads();
            }

            // ---- spline epilogue: one (row, dim) per thread
            const float* bo = boutg + (layer*DDIM + d)*PPD;
            float par[PPD];
#pragma unroll
            for (int p = 0; p < PPD; p++) {
                float2 u = unpack2(acc[p]);
                par[p] = u.x + u.y + bo[p];
            }
            float xraw = sm[cur + r*XPAD + d];
            float xo2, ldj;
            rqs_eval(par, xraw, xo2, ldj);
            sm[nxt + r*XPAD + (DDIM-1 - d)] = xo2;  // reversal fused
            ldacc += ldj;
        }

        int t = cur; cur = nxt; nxt = t;
    }

    __syncthreads();  // final-layer spline writes visible

    // ---- outputs: [xo (B*64) | ldf (B) | yo (B*64) | ldg (B)]
    const int xbase  = flow ? (BATCH*DDIM + BATCH) : 0;
    const int ldbase = flow ? (2*BATCH*DDIM + BATCH) : (BATCH*DDIM);

    for (int i = tid; i < TB*DDIM; i += NTHREADS) {
        int rr = i >> 6, dd = i & 63;
        out[xbase + row0*DDIM + i] = sm[cur + rr*XPAD + dd];
    }

    // log-det reduction: 4 partials (dl classes) per row
    float* red = &sm[OFF_WS];
    red[r*DG + dl] = ldacc;
    __syncthreads();
    if (tid < TB) {
        float s = red[tid*DG+0] + red[tid*DG+1] + red[tid*DG+2] + red[tid*DG+3];
        out[ldbase + row0 + tid] = s;
    }
}

// ---------------------------------------------------------------------------
extern "C" void kernel_launch(void* const* d_in, const int* in_sizes, int n_in,
                              void* d_out, int out_size)
{
    const float* x      = (const float*)d_in[0];
    const float* y      = (const float*)d_in[1];
    const float* f_W1   = (const float*)d_in[2];
    const float* f_b1   = (const float*)d_in[3];
    const float* f_Wout = (const float*)d_in[4];
    const float* f_bout = (const float*)d_in[5];
    const float* g_W1   = (const float*)d_in[6];
    const float* g_b1   = (const float*)d_in[7];
    const float* g_Wout = (const float*)d_in[8];
    const float* g_bout = (const float*)d_in[9];
    float* out = (float*)d_out;

    cudaFuncSetAttribute(maf_kernel, cudaFuncAttributeMaxDynamicSharedMemorySize, SMEM_BYTES);

    prep_kernel<<<1024, 256>>>(f_W1, f_Wout, g_W1, g_Wout);

    dim3 grid(BATCH/TB, 2);
    maf_kernel<<<grid, NTHREADS, SMEM_BYTES>>>(x, y, f_b1, f_bout, g_b1, g_bout, out);
}

// round 3
// speedup vs baseline: 2.3894x; 2.3894x over previous
#include <cuda_runtime.h>

#define LAYERS   8
#define WIDTH    128
#define DDIM     64
#define KNOTS    8
#define PPD      23          // 3*KNOTS-1
#define BATCH    16384
#define TB       64          // batch rows per CTA
#define NTHREADS 256
#define DG       16          // dims per chunk
#define NCHUNK   (DDIM/DG)   // 4
#define WSPAD    68          // padded row stride (floats), 68%32=4 -> conflict-free
#define XPAD     68
#define HPAD     132
#define BI       4.0f

// shared memory layout (float offsets)
#define OFF_X0   0
#define OFF_X1   (TB*XPAD)                    // 4352
#define OFF_H    (2*TB*XPAD)                  // 8704
#define OFF_WS   (2*TB*XPAD + TB*HPAD)        // 17152
#define WSROWS_MAX (DG*12)                    // 192 (pass A)
#define SMEM_FLOATS (OFF_WS + WSROWS_MAX*WSPAD)  // 30208
#define SMEM_BYTES  (SMEM_FLOATS*4)              // 120832 B

// Pre-masked, degree-sorted weights (static device scratch)
__device__ float g_W1m[2*LAYERS*WIDTH*DDIM];
__device__ float g_Wom[2*LAYERS*DDIM*PPD*WIDTH];
__device__ float g_b1p[2*LAYERS*WIDTH];

// ---------------------------------------------------------------------------
// packed fp32x2 FMA: 2 MACs per fma-pipe issue slot
// ---------------------------------------------------------------------------
__device__ __forceinline__ unsigned long long ffma2(unsigned long long a,
                                                    unsigned long long b,
                                                    unsigned long long c)
{
    unsigned long long d;
    asm("fma.rn.f32x2 %0, %1, %2, %3;" : "=l"(d) : "l"(a), "l"(b), "l"(c));
    return d;
}
__device__ __forceinline__ float2 unpack2(unsigned long long v)
{
    float2 r;
    asm("mov.b64 {%0, %1}, %2;" : "=f"(r.x), "=f"(r.y) : "l"(v));
    return r;
}

// ---------------------------------------------------------------------------
// Degree-sorted hidden permutation.
//   deg(w) = w % 63.  Sorted: j<6 -> deg j/3, else deg (j-2)/2.
//   perm(j) = original hidden index at sorted slot j.
// ---------------------------------------------------------------------------
__host__ __device__ __forceinline__ int sdeg(int j) { return (j < 6) ? (j/3) : ((j-2)>>1); }
__host__ __device__ __forceinline__ int permf(int j)
{
    if (j < 3)  return (j == 0) ? 0 : (j == 1 ? 63 : 126);
    if (j < 6)  return (j == 3) ? 1 : (j == 4 ? 64 : 127);
    int v = (j - 2) >> 1;
    return ((j & 1) == 0) ? v : v + 63;
}
// prefix length of dim d over sorted hidden, rounded up to 8
__device__ __forceinline__ int kmax_of(int d)
{
    int n = (d == 0) ? 0 : (d == 1 ? 3 : 2*d + 2);
    n = (n + 7) & ~7;
    return n > 128 ? 128 : n;
}

// ---------------------------------------------------------------------------
// Prep: mask + permute weights once per launch.
// ---------------------------------------------------------------------------
__global__ void prep_kernel(const float* __restrict__ fW1, const float* __restrict__ fWo,
                            const float* __restrict__ gW1, const float* __restrict__ gWo,
                            const float* __restrict__ fb1, const float* __restrict__ gb1)
{
    const int N1 = LAYERS*WIDTH*DDIM;
    const int N2 = LAYERS*DDIM*PPD*WIDTH;
    const int stride = gridDim.x * blockDim.x;
    const int t0 = blockIdx.x*blockDim.x + threadIdx.x;

    // W1: sorted rows, masked (row j keeps inputs c <= sdeg(j))
    for (int i = t0; i < 2*N1; i += stride) {
        int fl = i / N1, j = i - fl*N1;
        int row = (j >> 6) & (WIDTH-1);     // sorted slot
        int c = j & (DDIM-1);
        int l = j >> 13;                    // j / (WIDTH*DDIM)
        const float* s = fl ? gW1 : fW1;
        int src = permf(row);
        g_W1m[i] = (c <= sdeg(row)) ? s[l*WIDTH*DDIM + src*DDIM + c] : 0.f;
    }
    // Wout: sorted cols, masked (col j kept iff sdeg(j) < d) -> prefix support
    for (int i = t0; i < 2*N2; i += stride) {
        int fl = i / N2, j = i - fl*N2;
        int col = j & (WIDTH-1);            // sorted slot
        int o = (j >> 7) % (DDIM*PPD);
        int l = j / (DDIM*PPD*WIDTH);
        int d = o / PPD;
        const float* s = fl ? gWo : fWo;
        int src = permf(col);
        g_Wom[i] = (sdeg(col) < d) ? s[l*(DDIM*PPD)*WIDTH + o*WIDTH + src] : 0.f;
    }
    // b1 permuted
    for (int i = t0; i < 2*LAYERS*WIDTH; i += stride) {
        int fl = i / (LAYERS*WIDTH), j = i - fl*(LAYERS*WIDTH);
        int l = j >> 7, w = j & (WIDTH-1);
        const float* s = fl ? gb1 : fb1;
        g_b1p[i] = s[l*WIDTH + permf(w)];
    }
}

// ---------------------------------------------------------------------------
// Rational-quadratic spline (fully unrolled, register-resident)
// ---------------------------------------------------------------------------
__device__ __forceinline__ void rqs_eval(const float par[PPD], float xraw,
                                         float& xout, float& ldj)
{
    const float C1 = 8.0f / 1.01f;
    const float CADJ = 0.00125f;

    float mw = par[0];
#pragma unroll
    for (int j = 1; j < 8; j++) mw = fmaxf(mw, par[j]);
    float ew[8]; float sw = 0.f;
#pragma unroll
    for (int j = 0; j < 8; j++) { ew[j] = __expf(par[j] - mw); sw += ew[j]; }
    float isw = __frcp_rn(sw);

    float mh = par[8];
#pragma unroll
    for (int j = 1; j < 8; j++) mh = fmaxf(mh, par[8+j]);
    float eh[8]; float sh = 0.f;
#pragma unroll
    for (int j = 0; j < 8; j++) { eh[j] = __expf(par[8+j] - mh); sh += eh[j]; }
    float ish = __frcp_rn(sh);

    float sd[7];
#pragma unroll
    for (int j = 0; j < 7; j++) {
        float v = par[16+j];
        float sp = (v > 15.f) ? v : log1pf(__expf(v));
        sd[j] = sp + 0.001f;
    }

    float xc = fminf(fmaxf(xraw, -BI), BI);

    float xl = -BI, yl = -BI;
    float xk = 0.f, xk1 = 1.f, yk = 0.f, yk1 = 1.f, dk = 1.f, dk1 = 1.f;
    bool found = false;
#pragma unroll
    for (int j = 0; j < 8; j++) {
        float wj = (ew[j]*isw + CADJ) * C1;
        float hj = (eh[j]*ish + CADJ) * C1;
        float xr2 = xl + wj;
        float yr2 = yl + hj;
        bool sel = (!found) && ((xc < xr2) || (j == 7));
        if (sel) {
            xk = xl; xk1 = xr2; yk = yl; yk1 = yr2;
            dk  = (j == 0) ? 1.f : sd[j-1];
            dk1 = (j == 7) ? 1.f : sd[j];
            found = true;
        }
        xl = xr2; yl = yr2;
    }

    float invdx = __frcp_rn(xk1 - xk);
    float dyv = yk1 - yk;
    float sk  = dyv * invdx;
    float xi  = (xc - xk) * invdx;
    float omx = 1.f - xi;
    float xiomx = xi * omx;
    float den = sk + (dk1 + dk - 2.f*sk) * xiomx;
    float invden = __frcp_rn(den);
    float nume = sk*xi*xi + dk*xiomx;
    float outv = yk + dyv * nume * invden;
    float ldn = dk1*xi*xi + 2.f*sk*xiomx + dk*omx*omx;
    float ld = 2.f*__logf(sk) + __logf(ldn) - 2.f*__logf(den);

    bool inside = (xraw > -BI) && (xraw < BI);
    xout = inside ? outv : xraw;
    ldj  = inside ? ld : 0.f;
}

// ---------------------------------------------------------------------------
// GEMM2 pass: accumulate PCNT params for 4 rows (rg, rg+16, rg+32, rg+48)
// over this dim's K-prefix.  Stages its own W rows; FFMA2 K-packed.
// ---------------------------------------------------------------------------
template<int PBASE, int PCNT>
__device__ __forceinline__ void gemm2_pass(
    float* sm, const float* __restrict__ Wol,
    int d0, int dl, int rg, int chunkK, int kmax,
    float par[4][PPD])
{
    unsigned long long acc[4][PCNT];
#pragma unroll
    for (int ri = 0; ri < 4; ri++)
#pragma unroll
        for (int p = 0; p < PCNT; p++) acc[ri][p] = 0ull;

    for (int kh = 0; kh < 2; kh++) {
        if (kh*64 >= chunkK) break;                 // uniform over CTA
        const int halfK = min(64, chunkK - kh*64);
        const int hk4 = halfK >> 2;
        // stage W rows for this pass: DG*PCNT rows x halfK cols
        for (int i = threadIdx.x; i < DG*PCNT*hk4; i += NTHREADS) {
            int rr = i / hk4, c4 = i - rr*hk4;
            int dd = rr / PCNT, pp = rr - dd*PCNT;
            float4 v = *(const float4*)&Wol[((d0+dd)*PPD + PBASE + pp)*WIDTH + kh*64 + c4*4];
            *(float4*)&sm[OFF_WS + rr*WSPAD + c4*4] = v;
        }
        __syncthreads();

        int bound = kmax - kh*64;
        bound = bound < 0 ? 0 : (bound > halfK ? halfK : bound);
        const float* hbase = &sm[OFF_H + kh*64];
        const float* wsp   = &sm[OFF_WS + (dl*PCNT)*WSPAD];
#pragma unroll 4
        for (int k4 = 0; k4 < (bound >> 2); k4++) {
            ulonglong2 h0 = *(const ulonglong2*)&hbase[(rg     )*HPAD + k4*4];
            ulonglong2 h1 = *(const ulonglong2*)&hbase[(rg + 16)*HPAD + k4*4];
            ulonglong2 h2 = *(const ulonglong2*)&hbase[(rg + 32)*HPAD + k4*4];
            ulonglong2 h3 = *(const ulonglong2*)&hbase[(rg + 48)*HPAD + k4*4];
#pragma unroll
            for (int p = 0; p < PCNT; p++) {
                ulonglong2 wv = *(const ulonglong2*)&wsp[p*WSPAD + k4*4];
                acc[0][p] = ffma2(h0.x, wv.x, acc[0][p]);
                acc[0][p] = ffma2(h0.y, wv.y, acc[0][p]);
                acc[1][p] = ffma2(h1.x, wv.x, acc[1][p]);
                acc[1][p] = ffma2(h1.y, wv.y, acc[1][p]);
                acc[2][p] = ffma2(h2.x, wv.x, acc[2][p]);
                acc[2][p] = ffma2(h2.y, wv.y, acc[2][p]);
                acc[3][p] = ffma2(h3.x, wv.x, acc[3][p]);
                acc[3][p] = ffma2(h3.y, wv.y, acc[3][p]);
            }
        }
        __syncthreads();
    }

#pragma unroll
    for (int ri = 0; ri < 4; ri++)
#pragma unroll
        for (int p = 0; p < PCNT; p++) {
            float2 u = unpack2(acc[ri][p]);
            par[ri][PBASE + p] = u.x + u.y;
        }
}

// ---------------------------------------------------------------------------
// Main kernel: one CTA = 64 rows through all 8 layers. 1 CTA/SM.
// ---------------------------------------------------------------------------
__global__ __launch_bounds__(NTHREADS, 1)
void maf_kernel(const float* __restrict__ xin_f, const float* __restrict__ xin_g,
                const float* __restrict__ f_bout, const float* __restrict__ g_bout,
                float* __restrict__ out)
{
    extern __shared__ float sm[];
    const int tid  = threadIdx.x;
    const int flow = blockIdx.y;
    const int row0 = blockIdx.x * TB;

    const float* xin   = flow ? xin_g  : xin_f;
    const float* boutg = flow ? g_bout : f_bout;
    const float* b1p   = g_b1p + flow * (LAYERS*WIDTH);
    const float* W1m   = g_W1m + flow * (LAYERS*WIDTH*DDIM);
    const float* Wom   = g_Wom + flow * (LAYERS*DDIM*PPD*WIDTH);

    for (int i = tid; i < TB*DDIM; i += NTHREADS) {
        int r = i >> 6, d = i & 63;
        sm[OFF_X0 + r*XPAD + d] = xin[row0*DDIM + i];
    }

    const int rg = tid & 15;    // row group: handles rows rg+16*{0..3}
    const int dl = tid >> 4;    // dim lane within chunk (0..15); quarter-warp uniform

    float ldacc[4] = {0.f, 0.f, 0.f, 0.f};
    int cur = OFF_X0, nxt = OFF_X1;

    __syncthreads();

    for (int layer = 0; layer < LAYERS; layer++) {
        // ---- stage permuted+masked W1: 128 rows x 64 cols
        const float* W1l = W1m + layer*WIDTH*DDIM;
        for (int i = tid; i < WIDTH*DDIM/4; i += NTHREADS) {
            int w = i >> 4, c4 = i & 15;
            float4 v = ((const float4*)W1l)[i];
            *(float4*)&sm[OFF_WS + w*WSPAD + c4*4] = v;
        }
        __syncthreads();

        // ---- GEMM1: H = relu(X @ W1p^T + b1p), FFMA2 K-packed
        for (int it = 0; it < (TB*WIDTH)/NTHREADS; it++) {
            int idx = tid + it*NTHREADS;
            int rr = idx >> 7, w = idx & (WIDTH-1);
            const float* xr = &sm[cur + rr*XPAD];
            const float* wr = &sm[OFF_WS + w*WSPAD];
            unsigned long long a2 = 0ull;
#pragma unroll
            for (int iv = 0; iv < 16; iv++) {
                ulonglong2 xv = *(const ulonglong2*)&xr[iv*4];
                ulonglong2 wv = *(const ulonglong2*)&wr[iv*4];
                a2 = ffma2(xv.x, wv.x, a2);
                a2 = ffma2(xv.y, wv.y, a2);
            }
            float2 p2 = unpack2(a2);
            float a = p2.x + p2.y + b1p[layer*WIDTH + w];
            sm[OFF_H + rr*HPAD + w] = fmaxf(a, 0.f);
        }
        __syncthreads();

        // ---- GEMM2 + spline over 4 chunks of 16 dims
        for (int chunk = 0; chunk < NCHUNK; chunk++) {
            const int d0 = chunk * DG;
            const int d  = d0 + dl;
            const int kmax   = kmax_of(d);
            const int chunkK = kmax_of(d0 + 15);
            const float* Wol = Wom + layer*DDIM*PPD*WIDTH;

            float par[4][PPD];
            gemm2_pass<0, 12>(sm, Wol, d0, dl, rg, chunkK, kmax, par);
            gemm2_pass<12, 11>(sm, Wol, d0, dl, rg, chunkK, kmax, par);

            // bias for this dim
            const float* bo = boutg + (layer*DDIM + d)*PPD;
            float bor[PPD];
#pragma unroll
            for (int p = 0; p < PPD; p++) bor[p] = bo[p];

#pragma unroll
            for (int ri = 0; ri < 4; ri++) {
                const int r = rg + 16*ri;
                float parr[PPD];
#pragma unroll
                for (int p = 0; p < PPD; p++) parr[p] = par[ri][p] + bor[p];
                float xraw = sm[cur + r*XPAD + d];
                float xo2, ldj;
                rqs_eval(parr, xraw, xo2, ldj);
                sm[nxt + r*XPAD + (DDIM-1 - d)] = xo2;   // reversal fused
                ldacc[ri] += ldj;
            }
        }

        int t = cur; cur = nxt; nxt = t;
    }

    __syncthreads();

    // ---- outputs: [xo (B*64) | ldf (B) | yo (B*64) | ldg (B)]
    const int xbase  = flow ? (BATCH*DDIM + BATCH) : 0;
    const int ldbase = flow ? (2*BATCH*DDIM + BATCH) : (BATCH*DDIM);

    for (int i = tid; i < TB*DDIM; i += NTHREADS) {
        int rr = i >> 6, dd = i & 63;
        out[xbase + row0*DDIM + i] = sm[cur + rr*XPAD + dd];
    }

    // log-det reduction: 16 dim-class partials per row
    float* red = &sm[OFF_WS];
#pragma unroll
    for (int ri = 0; ri < 4; ri++)
        red[(rg + 16*ri)*16 + dl] = ldacc[ri];
    __syncthreads();
    if (tid < TB) {
        float s = 0.f;
#pragma unroll
        for (int j = 0; j < 16; j++) s += red[tid*16 + j];
        out[ldbase + row0 + tid] = s;
    }
}

// ---------------------------------------------------------------------------
extern "C" void kernel_launch(void* const* d_in, const int* in_sizes, int n_in,
                              void* d_out, int out_size)
{
    const float* x      = (const float*)d_in[0];
    const float* y      = (const float*)d_in[1];
    const float* f_W1   = (const float*)d_in[2];
    const float* f_b1   = (const float*)d_in[3];
    const float* f_Wout = (const float*)d_in[4];
    const float* f_bout = (const float*)d_in[5];
    const float* g_W1   = (const float*)d_in[6];
    const float* g_b1   = (const float*)d_in[7];
    const float* g_Wout = (const float*)d_in[8];
    const float* g_bout = (const float*)d_in[9];
    float* out = (float*)d_out;

    cudaFuncSetAttribute(maf_kernel, cudaFuncAttributeMaxDynamicSharedMemorySize, SMEM_BYTES);

    prep_kernel<<<1024, 256>>>(f_W1, f_Wout, g_W1, g_Wout, f_b1, g_b1);

    dim3 grid(BATCH/TB, 2);
    maf_kernel<<<grid, NTHREADS, SMEM_BYTES>>>(x, y, f_bout, g_bout, out);
}

// round 4
// speedup vs baseline: 2.8956x; 1.2119x over previous
#include <cuda_runtime.h>

#define LAYERS   8
#define WIDTH    128
#define DDIM     64
#define KNOTS    8
#define PPD      23          // 3*KNOTS-1
#define BATCH    16384
#define TB       64          // batch rows per CTA
#define NTHREADS 256
#define DG       16          // dims per chunk
#define NCHUNK   (DDIM/DG)   // 4
#define WSPAD    68          // padded row stride (floats), conflict-free
#define XPAD     68
#define HPAD     132
#define BI       4.0f

// shared memory layout (float offsets)
#define OFF_X0   0
#define OFF_X1   (TB*XPAD)                    // 4352
#define OFF_H    (2*TB*XPAD)                  // 8704
#define OFF_WS   (2*TB*XPAD + TB*HPAD)        // 17152
#define WSROWS_MAX (DG*8)                     // 128 rows (max pass size)
#define SMEM_FLOATS (OFF_WS + WSROWS_MAX*WSPAD)  // 17152 + 8704 = 25856
#define SMEM_BYTES  (SMEM_FLOATS*4)              // 103424 B -> 2 CTAs/SM

// Pre-masked, degree-sorted weights (static device scratch)
__device__ float g_W1m[2*LAYERS*WIDTH*DDIM];
__device__ float g_Wom[2*LAYERS*DDIM*PPD*WIDTH];
__device__ float g_b1p[2*LAYERS*WIDTH];

// ---------------------------------------------------------------------------
// packed fp32x2 FMA: 2 MACs per fma-pipe issue slot
// ---------------------------------------------------------------------------
__device__ __forceinline__ unsigned long long ffma2(unsigned long long a,
                                                    unsigned long long b,
                                                    unsigned long long c)
{
    unsigned long long d;
    asm("fma.rn.f32x2 %0, %1, %2, %3;" : "=l"(d) : "l"(a), "l"(b), "l"(c));
    return d;
}
__device__ __forceinline__ float2 unpack2(unsigned long long v)
{
    float2 r;
    asm("mov.b64 {%0, %1}, %2;" : "=f"(r.x), "=f"(r.y) : "l"(v));
    return r;
}

// ---------------------------------------------------------------------------
// Degree-sorted hidden permutation.
//   deg(w) = w % 63.  sorted slot j has degree sdeg(j); permf(j) = source idx.
// ---------------------------------------------------------------------------
__host__ __device__ __forceinline__ int sdeg(int j) { return (j < 6) ? (j/3) : ((j-2)>>1); }
__host__ __device__ __forceinline__ int permf(int j)
{
    if (j < 3)  return (j == 0) ? 0 : (j == 1 ? 63 : 126);
    if (j < 6)  return (j == 3) ? 1 : (j == 4 ? 64 : 127);
    int v = (j - 2) >> 1;
    return ((j & 1) == 0) ? v : v + 63;
}
// prefix length of dim d over sorted hidden, rounded up to 8
__device__ __forceinline__ int kmax_of(int d)
{
    int n = (d == 0) ? 0 : (d == 1 ? 3 : 2*d + 2);
    n = (n + 7) & ~7;
    return n > 128 ? 128 : n;
}

// ---------------------------------------------------------------------------
// Prep: mask + permute weights once per launch.
// ---------------------------------------------------------------------------
__global__ void prep_kernel(const float* __restrict__ fW1, const float* __restrict__ fWo,
                            const float* __restrict__ gW1, const float* __restrict__ gWo,
                            const float* __restrict__ fb1, const float* __restrict__ gb1)
{
    const int N1 = LAYERS*WIDTH*DDIM;
    const int N2 = LAYERS*DDIM*PPD*WIDTH;
    const int stride = gridDim.x * blockDim.x;
    const int t0 = blockIdx.x*blockDim.x + threadIdx.x;

    for (int i = t0; i < 2*N1; i += stride) {
        int fl = i / N1, j = i - fl*N1;
        int row = (j >> 6) & (WIDTH-1);
        int c = j & (DDIM-1);
        int l = j >> 13;
        const float* s = fl ? gW1 : fW1;
        int src = permf(row);
        g_W1m[i] = (c <= sdeg(row)) ? s[l*WIDTH*DDIM + src*DDIM + c] : 0.f;
    }
    for (int i = t0; i < 2*N2; i += stride) {
        int fl = i / N2, j = i - fl*N2;
        int col = j & (WIDTH-1);
        int o = (j >> 7) % (DDIM*PPD);
        int l = j / (DDIM*PPD*WIDTH);
        int d = o / PPD;
        const float* s = fl ? gWo : fWo;
        int src = permf(col);
        g_Wom[i] = (sdeg(col) < d) ? s[l*(DDIM*PPD)*WIDTH + o*WIDTH + src] : 0.f;
    }
    for (int i = t0; i < 2*LAYERS*WIDTH; i += stride) {
        int fl = i / (LAYERS*WIDTH), j = i - fl*(LAYERS*WIDTH);
        int l = j >> 7, w = j & (WIDTH-1);
        const float* s = fl ? gb1 : fb1;
        g_b1p[i] = s[l*WIDTH + permf(w)];
    }
}

// ---------------------------------------------------------------------------
// GEMM2 pass: PCNT params x 4 rows over this dim's K-prefix; FFMA2 K-packed.
// Result (bias added) written to out[ri][0..PCNT).
// ---------------------------------------------------------------------------
template<int PBASE, int PCNT>
__device__ __forceinline__ void gemm2_pass(
    float* sm, const float* __restrict__ Wol, const float* __restrict__ bo,
    int d0, int dl, int rg, int chunkK, int kmax, float out[4][8])
{
    unsigned long long acc[4][PCNT];
#pragma unroll
    for (int ri = 0; ri < 4; ri++)
#pragma unroll
        for (int p = 0; p < PCNT; p++) acc[ri][p] = 0ull;

    for (int kh = 0; kh < 2; kh++) {
        if (kh*64 >= chunkK) break;                 // uniform over CTA
        const int halfK = min(64, chunkK - kh*64);
        const int hk4 = halfK >> 2;
        const int shf = (hk4 == 8) ? 3 : 4;
        // stage W rows for this pass: DG*PCNT rows x halfK cols
        for (int i = threadIdx.x; i < DG*PCNT*hk4; i += NTHREADS) {
            int rr = i >> shf, c4 = i & (hk4 - 1);
            int dd = rr / PCNT, pp = rr - dd*PCNT;
            float4 v = *(const float4*)&Wol[((d0+dd)*PPD + PBASE + pp)*WIDTH + kh*64 + c4*4];
            *(float4*)&sm[OFF_WS + rr*WSPAD + c4*4] = v;
        }
        __syncthreads();

        int bound = kmax - kh*64;
        bound = bound < 0 ? 0 : (bound > halfK ? halfK : bound);
        const float* hbase = &sm[OFF_H + kh*64];
        const float* wsp   = &sm[OFF_WS + (dl*PCNT)*WSPAD];
#pragma unroll 2
        for (int k4 = 0; k4 < (bound >> 2); k4++) {
            ulonglong2 h0 = *(const ulonglong2*)&hbase[(rg     )*HPAD + k4*4];
            ulonglong2 h1 = *(const ulonglong2*)&hbase[(rg + 16)*HPAD + k4*4];
            ulonglong2 h2 = *(const ulonglong2*)&hbase[(rg + 32)*HPAD + k4*4];
            ulonglong2 h3 = *(const ulonglong2*)&hbase[(rg + 48)*HPAD + k4*4];
#pragma unroll
            for (int p = 0; p < PCNT; p++) {
                ulonglong2 wv = *(const ulonglong2*)&wsp[p*WSPAD + k4*4];
                acc[0][p] = ffma2(h0.x, wv.x, acc[0][p]);
                acc[0][p] = ffma2(h0.y, wv.y, acc[0][p]);
                acc[1][p] = ffma2(h1.x, wv.x, acc[1][p]);
                acc[1][p] = ffma2(h1.y, wv.y, acc[1][p]);
                acc[2][p] = ffma2(h2.x, wv.x, acc[2][p]);
                acc[2][p] = ffma2(h2.y, wv.y, acc[2][p]);
                acc[3][p] = ffma2(h3.x, wv.x, acc[3][p]);
                acc[3][p] = ffma2(h3.y, wv.y, acc[3][p]);
            }
        }
        __syncthreads();
    }

#pragma unroll
    for (int ri = 0; ri < 4; ri++)
#pragma unroll
        for (int p = 0; p < PCNT; p++) {
            float2 u = unpack2(acc[ri][p]);
            out[ri][p] = u.x + u.y + bo[PBASE + p];
        }
}

// ---------------------------------------------------------------------------
// Main kernel: one CTA = 64 rows through all 8 layers; 2 CTAs/SM.
// Spline is evaluated in 3 streamed phases (widths/heights/derivs) so the
// 23-param vector never lives in registers all at once.
// ---------------------------------------------------------------------------
__global__ __launch_bounds__(NTHREADS, 2)
void maf_kernel(const float* __restrict__ xin_f, const float* __restrict__ xin_g,
                const float* __restrict__ f_bout, const float* __restrict__ g_bout,
                float* __restrict__ out)
{
    extern __shared__ float sm[];
    const int tid  = threadIdx.x;
    const int flow = blockIdx.y;
    const int row0 = blockIdx.x * TB;

    const float* xin   = flow ? xin_g  : xin_f;
    const float* boutg = flow ? g_bout : f_bout;
    const float* b1p   = g_b1p + flow * (LAYERS*WIDTH);
    const float* W1m   = g_W1m + flow * (LAYERS*WIDTH*DDIM);
    const float* Wom   = g_Wom + flow * (LAYERS*DDIM*PPD*WIDTH);

    for (int i = tid; i < TB*DDIM; i += NTHREADS) {
        int r = i >> 6, d = i & 63;
        sm[OFF_X0 + r*XPAD + d] = xin[row0*DDIM + i];
    }

    const int rg = tid & 15;    // row group: rows rg + 16*{0..3}
    const int dl = tid >> 4;    // dim lane within chunk (0..15)

    const float C1 = 8.0f / 1.01f;
    const float CADJ = 0.00125f;

    float ldacc[4] = {0.f, 0.f, 0.f, 0.f};
    int cur = OFF_X0, nxt = OFF_X1;

    __syncthreads();

    for (int layer = 0; layer < LAYERS; layer++) {
        // ---- stage permuted+masked W1: 128 rows x 64 cols
        const float* W1l = W1m + layer*WIDTH*DDIM;
        for (int i = tid; i < WIDTH*DDIM/4; i += NTHREADS) {
            int w = i >> 4, c4 = i & 15;
            float4 v = ((const float4*)W1l)[i];
            *(float4*)&sm[OFF_WS + w*WSPAD + c4*4] = v;
        }
        __syncthreads();

        // ---- GEMM1: H = relu(X @ W1p^T + b1p), FFMA2 K-packed
        for (int it = 0; it < (TB*WIDTH)/NTHREADS; it++) {
            int idx = tid + it*NTHREADS;
            int rr = idx >> 7, w = idx & (WIDTH-1);
            const float* xr = &sm[cur + rr*XPAD];
            const float* wr = &sm[OFF_WS + w*WSPAD];
            unsigned long long a2 = 0ull;
#pragma unroll
            for (int iv = 0; iv < 16; iv++) {
                ulonglong2 xv = *(const ulonglong2*)&xr[iv*4];
                ulonglong2 wv = *(const ulonglong2*)&wr[iv*4];
                a2 = ffma2(xv.x, wv.x, a2);
                a2 = ffma2(xv.y, wv.y, a2);
            }
            float2 p2 = unpack2(a2);
            float a = p2.x + p2.y + b1p[layer*WIDTH + w];
            sm[OFF_H + rr*HPAD + w] = fmaxf(a, 0.f);
        }
        __syncthreads();

        // ---- GEMM2 + streamed spline over 4 chunks of 16 dims
        for (int chunk = 0; chunk < NCHUNK; chunk++) {
            const int d0 = chunk * DG;
            const int d  = d0 + dl;
            const int kmax   = kmax_of(d);
            const int chunkK = kmax_of(d0 + 15);
            const float* Wol = Wom + layer*DDIM*PPD*WIDTH;
            const float* bo  = boutg + (layer*DDIM + d)*PPD;

            float pr[4][8];
            float st_xraw[4], st_xi[4], st_invdx[4], st_yk[4], st_dyv[4], st_sk[4];
            int   st_k[4];

            // ===== phase 1: widths -> bin index, xi, invdx =====
            gemm2_pass<0, 8>(sm, Wol, bo, d0, dl, rg, chunkK, kmax, pr);
#pragma unroll
            for (int ri = 0; ri < 4; ri++) {
                float mw = pr[ri][0];
#pragma unroll
                for (int j = 1; j < 8; j++) mw = fmaxf(mw, pr[ri][j]);
                float ew[8]; float swv = 0.f;
#pragma unroll
                for (int j = 0; j < 8; j++) { ew[j] = __expf(pr[ri][j] - mw); swv += ew[j]; }
                float isw = __frcp_rn(swv);

                float xraw = sm[cur + (rg + 16*ri)*XPAD + d];
                float xc = fminf(fmaxf(xraw, -BI), BI);

                float xl = -BI;
                float xk = 0.f, xk1 = 1.f;
                int k = 7; bool found = false;
#pragma unroll
                for (int j = 0; j < 8; j++) {
                    float wj = (ew[j]*isw + CADJ) * C1;
                    float xr2 = xl + wj;
                    bool sel = (!found) && ((xc < xr2) || (j == 7));
                    if (sel) { k = j; xk = xl; xk1 = xr2; found = true; }
                    xl = xr2;
                }
                float invdx = __frcp_rn(xk1 - xk);
                st_xraw[ri] = xraw;
                st_invdx[ri] = invdx;
                st_xi[ri] = (xc - xk) * invdx;
                st_k[ri] = k;
            }

            // ===== phase 2: heights -> yk, dyv, sk =====
            gemm2_pass<8, 8>(sm, Wol, bo, d0, dl, rg, chunkK, kmax, pr);
#pragma unroll
            for (int ri = 0; ri < 4; ri++) {
                float mh = pr[ri][0];
#pragma unroll
                for (int j = 1; j < 8; j++) mh = fmaxf(mh, pr[ri][j]);
                float eh[8]; float shv = 0.f;
#pragma unroll
                for (int j = 0; j < 8; j++) { eh[j] = __expf(pr[ri][j] - mh); shv += eh[j]; }
                float ish = __frcp_rn(shv);

                const int k = st_k[ri];
                float yl = -BI;
                float yk = 0.f, yk1 = 1.f;
#pragma unroll
                for (int j = 0; j < 8; j++) {
                    float hj = (eh[j]*ish + CADJ) * C1;
                    float yr2 = yl + hj;
                    if (j == k) { yk = yl; yk1 = yr2; }
                    yl = yr2;
                }
                st_yk[ri] = yk;
                st_dyv[ri] = yk1 - yk;
                st_sk[ri] = st_dyv[ri] * st_invdx[ri];
            }

            // ===== phase 3: derivatives -> finish spline =====
            gemm2_pass<16, 7>(sm, Wol, bo, d0, dl, rg, chunkK, kmax, pr);
#pragma unroll
            for (int ri = 0; ri < 4; ri++) {
                const int k = st_k[ri];
                float dk = 1.f, dk1 = 1.f;
#pragma unroll
                for (int j = 0; j < 7; j++) {
                    float v = pr[ri][j];
                    float sp = (v > 15.f) ? v : log1pf(__expf(v));
                    float sdv = sp + 0.001f;
                    if (j == k - 1) dk  = sdv;
                    if (j == k)     dk1 = sdv;
                }
                float xi = st_xi[ri];
                float omx = 1.f - xi;
                float xiomx = xi * omx;
                float sk = st_sk[ri];
                float den = sk + (dk1 + dk - 2.f*sk) * xiomx;
                float invden = __frcp_rn(den);
                float nume = sk*xi*xi + dk*xiomx;
                float outv = st_yk[ri] + st_dyv[ri] * nume * invden;
                float ldn = dk1*xi*xi + 2.f*sk*xiomx + dk*omx*omx;
                float ld = 2.f*__logf(sk) + __logf(ldn) - 2.f*__logf(den);

                float xraw = st_xraw[ri];
                bool inside = (xraw > -BI) && (xraw < BI);
                float xo2 = inside ? outv : xraw;
                sm[nxt + (rg + 16*ri)*XPAD + (DDIM-1 - d)] = xo2;  // reversal fused
                ldacc[ri] += inside ? ld : 0.f;
            }
        }

        int t = cur; cur = nxt; nxt = t;
    }

    __syncthreads();

    // ---- outputs: [xo (B*64) | ldf (B) | yo (B*64) | ldg (B)]
    const int xbase  = flow ? (BATCH*DDIM + BATCH) : 0;
    const int ldbase = flow ? (2*BATCH*DDIM + BATCH) : (BATCH*DDIM);

    for (int i = tid; i < TB*DDIM; i += NTHREADS) {
        int rr = i >> 6, dd = i & 63;
        out[xbase + row0*DDIM + i] = sm[cur + rr*XPAD + dd];
    }

    // log-det reduction: 16 dim-class partials per row
    float* red = &sm[OFF_WS];
#pragma unroll
    for (int ri = 0; ri < 4; ri++)
        red[(rg + 16*ri)*16 + dl] = ldacc[ri];
    __syncthreads();
    if (tid < TB) {
        float s = 0.f;
#pragma unroll
        for (int j = 0; j < 16; j++) s += red[tid*16 + j];
        out[ldbase + row0 + tid] = s;
    }
}

// ---------------------------------------------------------------------------
extern "C" void kernel_launch(void* const* d_in, const int* in_sizes, int n_in,
                              void* d_out, int out_size)
{
    const float* x      = (const float*)d_in[0];
    const float* y      = (const float*)d_in[1];
    const float* f_W1   = (const float*)d_in[2];
    const float* f_b1   = (const float*)d_in[3];
    const float* f_Wout = (const float*)d_in[4];
    const float* f_bout = (const float*)d_in[5];
    const float* g_W1   = (const float*)d_in[6];
    const float* g_b1   = (const float*)d_in[7];
    const float* g_Wout = (const float*)d_in[8];
    const float* g_bout = (const float*)d_in[9];
    float* out = (float*)d_out;

    cudaFuncSetAttribute(maf_kernel, cudaFuncAttributeMaxDynamicSharedMemorySize, SMEM_BYTES);

    prep_kernel<<<1024, 256>>>(f_W1, f_Wout, g_W1, g_Wout, f_b1, g_b1);

    dim3 grid(BATCH/TB, 2);
    maf_kernel<<<grid, NTHREADS, SMEM_BYTES>>>(x, y, f_bout, g_bout, out);
}

// round 5
// speedup vs baseline: 3.1353x; 1.0828x over previous
#include <cuda_runtime.h>

#define LAYERS   8
#define WIDTH    128
#define DDIM     64
#define KNOTS    8
#define PPD      23          // 3*KNOTS-1
#define BATCH    16384
#define TB       64          // batch rows per CTA
#define NTHREADS 256
#define DG       16          // dims per chunk
#define NCHUNK   (DDIM/DG)   // 4
#define WSPAD    68          // padded row stride (floats), conflict-free
#define XPAD     68
#define HPAD     132
#define BI       4.0f

// shared memory layout (float offsets)
#define OFF_X0   0
#define OFF_X1   (TB*XPAD)                    // 4352
#define OFF_H    (2*TB*XPAD)                  // 8704
#define OFF_WS   (2*TB*XPAD + TB*HPAD)        // 17152
#define WSROWS_MAX (DG*8)                     // 128 rows (max pass size)
#define OFF_B1   (OFF_WS + WSROWS_MAX*WSPAD)  // 25856
#define SMEM_FLOATS (OFF_B1 + WIDTH)          // 25984
#define SMEM_BYTES  (SMEM_FLOATS*4)           // 103936 B -> 2 CTAs/SM

// Pre-masked, degree-sorted weights (static device scratch)
__device__ float g_W1m[2*LAYERS*WIDTH*DDIM];
__device__ float g_Wom[2*LAYERS*DDIM*PPD*WIDTH];
__device__ float g_b1p[2*LAYERS*WIDTH];

// ---------------------------------------------------------------------------
// packed fp32x2 FMA: 2 MACs per fma-pipe issue slot
// ---------------------------------------------------------------------------
__device__ __forceinline__ unsigned long long ffma2(unsigned long long a,
                                                    unsigned long long b,
                                                    unsigned long long c)
{
    unsigned long long d;
    asm("fma.rn.f32x2 %0, %1, %2, %3;" : "=l"(d) : "l"(a), "l"(b), "l"(c));
    return d;
}
__device__ __forceinline__ float2 unpack2(unsigned long long v)
{
    float2 r;
    asm("mov.b64 {%0, %1}, %2;" : "=f"(r.x), "=f"(r.y) : "l"(v));
    return r;
}

// ---------------------------------------------------------------------------
// Degree-sorted hidden permutation.
//   deg(w) = w % 63.  sorted slot j has degree sdeg(j); permf(j) = source idx.
// ---------------------------------------------------------------------------
__host__ __device__ __forceinline__ int sdeg(int j) { return (j < 6) ? (j/3) : ((j-2)>>1); }
__host__ __device__ __forceinline__ int permf(int j)
{
    if (j < 3)  return (j == 0) ? 0 : (j == 1 ? 63 : 126);
    if (j < 6)  return (j == 3) ? 1 : (j == 4 ? 64 : 127);
    int v = (j - 2) >> 1;
    return ((j & 1) == 0) ? v : v + 63;
}
// prefix length of dim d over sorted hidden, rounded up to 8
__device__ __forceinline__ int kmax_of(int d)
{
    int n = (d == 0) ? 0 : (d == 1 ? 3 : 2*d + 2);
    n = (n + 7) & ~7;
    return n > 128 ? 128 : n;
}

// ---------------------------------------------------------------------------
// Prep: mask + permute weights once per launch.
// ---------------------------------------------------------------------------
__global__ void prep_kernel(const float* __restrict__ fW1, const float* __restrict__ fWo,
                            const float* __restrict__ gW1, const float* __restrict__ gWo,
                            const float* __restrict__ fb1, const float* __restrict__ gb1)
{
    const int N1 = LAYERS*WIDTH*DDIM;
    const int N2 = LAYERS*DDIM*PPD*WIDTH;
    const int stride = gridDim.x * blockDim.x;
    const int t0 = blockIdx.x*blockDim.x + threadIdx.x;

    for (int i = t0; i < 2*N1; i += stride) {
        int fl = i / N1, j = i - fl*N1;
        int row = (j >> 6) & (WIDTH-1);
        int c = j & (DDIM-1);
        int l = j >> 13;
        const float* s = fl ? gW1 : fW1;
        int src = permf(row);
        g_W1m[i] = (c <= sdeg(row)) ? s[l*WIDTH*DDIM + src*DDIM + c] : 0.f;
    }
    for (int i = t0; i < 2*N2; i += stride) {
        int fl = i / N2, j = i - fl*N2;
        int col = j & (WIDTH-1);
        int o = (j >> 7) % (DDIM*PPD);
        int l = j / (DDIM*PPD*WIDTH);
        int d = o / PPD;
        const float* s = fl ? gWo : fWo;
        int src = permf(col);
        g_Wom[i] = (sdeg(col) < d) ? s[l*(DDIM*PPD)*WIDTH + o*WIDTH + src] : 0.f;
    }
    for (int i = t0; i < 2*LAYERS*WIDTH; i += stride) {
        int fl = i / (LAYERS*WIDTH), j = i - fl*(LAYERS*WIDTH);
        int l = j >> 7, w = j & (WIDTH-1);
        const float* s = fl ? gb1 : fb1;
        g_b1p[i] = s[l*WIDTH + permf(w)];
    }
}

// ---------------------------------------------------------------------------
// GEMM2 pass: PCNT params x 4 rows over this dim's K-prefix; FFMA2 K-packed.
// Result (bias added) written to out[ri][0..PCNT).
// ---------------------------------------------------------------------------
template<int PBASE, int PCNT>
__device__ __forceinline__ void gemm2_pass(
    float* sm, const float* __restrict__ Wol, const float* __restrict__ bo,
    int d0, int dl, int rg, int chunkK, int kmax, float out[4][8])
{
    unsigned long long acc[4][PCNT];
#pragma unroll
    for (int ri = 0; ri < 4; ri++)
#pragma unroll
        for (int p = 0; p < PCNT; p++) acc[ri][p] = 0ull;

    for (int kh = 0; kh < 2; kh++) {
        if (kh*64 >= chunkK) break;                 // uniform over CTA
        const int halfK = min(64, chunkK - kh*64);
        const int hk4 = halfK >> 2;
        const int shf = (hk4 == 8) ? 3 : 4;
        // stage W rows for this pass: DG*PCNT rows x halfK cols
        for (int i = threadIdx.x; i < DG*PCNT*hk4; i += NTHREADS) {
            int rr = i >> shf, c4 = i & (hk4 - 1);
            int dd = rr / PCNT, pp = rr - dd*PCNT;
            float4 v = *(const float4*)&Wol[((d0+dd)*PPD + PBASE + pp)*WIDTH + kh*64 + c4*4];
            *(float4*)&sm[OFF_WS + rr*WSPAD + c4*4] = v;
        }
        __syncthreads();

        int bound = kmax - kh*64;
        bound = bound < 0 ? 0 : (bound > halfK ? halfK : bound);
        const float* hbase = &sm[OFF_H + kh*64];
        const float* wsp   = &sm[OFF_WS + (dl*PCNT)*WSPAD];
#pragma unroll 2
        for (int k4 = 0; k4 < (bound >> 2); k4++) {
            ulonglong2 h0 = *(const ulonglong2*)&hbase[(rg     )*HPAD + k4*4];
            ulonglong2 h1 = *(const ulonglong2*)&hbase[(rg + 16)*HPAD + k4*4];
            ulonglong2 h2 = *(const ulonglong2*)&hbase[(rg + 32)*HPAD + k4*4];
            ulonglong2 h3 = *(const ulonglong2*)&hbase[(rg + 48)*HPAD + k4*4];
#pragma unroll
            for (int p = 0; p < PCNT; p++) {
                ulonglong2 wv = *(const ulonglong2*)&wsp[p*WSPAD + k4*4];
                acc[0][p] = ffma2(h0.x, wv.x, acc[0][p]);
                acc[0][p] = ffma2(h0.y, wv.y, acc[0][p]);
                acc[1][p] = ffma2(h1.x, wv.x, acc[1][p]);
                acc[1][p] = ffma2(h1.y, wv.y, acc[1][p]);
                acc[2][p] = ffma2(h2.x, wv.x, acc[2][p]);
                acc[2][p] = ffma2(h2.y, wv.y, acc[2][p]);
                acc[3][p] = ffma2(h3.x, wv.x, acc[3][p]);
                acc[3][p] = ffma2(h3.y, wv.y, acc[3][p]);
            }
        }
        __syncthreads();
    }

#pragma unroll
    for (int ri = 0; ri < 4; ri++)
#pragma unroll
        for (int p = 0; p < PCNT; p++) {
            float2 u = unpack2(acc[ri][p]);
            out[ri][p] = u.x + u.y + bo[PBASE + p];
        }
}

// ---------------------------------------------------------------------------
// Main kernel: one CTA = 64 rows through all 8 layers; 2 CTAs/SM.
// GEMM1: 4 rows x 8 hidden per thread, W broadcast within quarter-warp,
// K-prefix sparsity.  Spline streamed in 3 phases.
// ---------------------------------------------------------------------------
__global__ __launch_bounds__(NTHREADS, 2)
void maf_kernel(const float* __restrict__ xin_f, const float* __restrict__ xin_g,
                const float* __restrict__ f_bout, const float* __restrict__ g_bout,
                float* __restrict__ out)
{
    extern __shared__ float sm[];
    const int tid  = threadIdx.x;
    const int flow = blockIdx.y;
    const int row0 = blockIdx.x * TB;

    const float* xin   = flow ? xin_g  : xin_f;
    const float* boutg = flow ? g_bout : f_bout;
    const float* b1p   = g_b1p + flow * (LAYERS*WIDTH);
    const float* W1m   = g_W1m + flow * (LAYERS*WIDTH*DDIM);
    const float* Wom   = g_Wom + flow * (LAYERS*DDIM*PPD*WIDTH);

    for (int i = tid; i < TB*DDIM; i += NTHREADS) {
        int r = i >> 6, d = i & 63;
        sm[OFF_X0 + r*XPAD + d] = xin[row0*DDIM + i];
    }

    const int rg = tid & 15;    // row lane (GEMM2 & GEMM1): rows rg + 16*{0..3}
    const int dl = tid >> 4;    // GEMM2: dim lane; GEMM1: hidden group wq
    const int wq = dl;

    const float C1 = 8.0f / 1.01f;
    const float CADJ = 0.00125f;

    float ldacc[4] = {0.f, 0.f, 0.f, 0.f};
    int cur = OFF_X0, nxt = OFF_X1;

    __syncthreads();

    for (int layer = 0; layer < LAYERS; layer++) {
        // ---- stage permuted+masked W1 (128 x 64) + b1
        const float* W1l = W1m + layer*WIDTH*DDIM;
        for (int i = tid; i < WIDTH*DDIM/4; i += NTHREADS) {
            int w = i >> 4, c4 = i & 15;
            float4 v = ((const float4*)W1l)[i];
            *(float4*)&sm[OFF_WS + w*WSPAD + c4*4] = v;
        }
        if (tid < WIDTH) sm[OFF_B1 + tid] = b1p[layer*WIDTH + tid];
        __syncthreads();

        // ---- GEMM1: H = relu(X @ W1p^T + b1p); 4 rows x 8 hidden per thread.
        // Hidden group wq has input prefix kmax = 4*wq+4 (zeros beyond mask).
        {
            unsigned long long acc[4][8];
#pragma unroll
            for (int ri = 0; ri < 4; ri++)
#pragma unroll
                for (int p = 0; p < 8; p++) acc[ri][p] = 0ull;

            const float* wsp = &sm[OFF_WS + (wq*8)*WSPAD];
            const int kb = wq + 1;          // k4 iterations
#pragma unroll 2
            for (int k4 = 0; k4 < kb; k4++) {
                ulonglong2 x0 = *(const ulonglong2*)&sm[cur + (rg     )*XPAD + k4*4];
                ulonglong2 x1 = *(const ulonglong2*)&sm[cur + (rg + 16)*XPAD + k4*4];
                ulonglong2 x2 = *(const ulonglong2*)&sm[cur + (rg + 32)*XPAD + k4*4];
                ulonglong2 x3 = *(const ulonglong2*)&sm[cur + (rg + 48)*XPAD + k4*4];
#pragma unroll
                for (int p = 0; p < 8; p++) {
                    ulonglong2 wv = *(const ulonglong2*)&wsp[p*WSPAD + k4*4];
                    acc[0][p] = ffma2(x0.x, wv.x, acc[0][p]);
                    acc[0][p] = ffma2(x0.y, wv.y, acc[0][p]);
                    acc[1][p] = ffma2(x1.x, wv.x, acc[1][p]);
                    acc[1][p] = ffma2(x1.y, wv.y, acc[1][p]);
                    acc[2][p] = ffma2(x2.x, wv.x, acc[2][p]);
                    acc[2][p] = ffma2(x2.y, wv.y, acc[2][p]);
                    acc[3][p] = ffma2(x3.x, wv.x, acc[3][p]);
                    acc[3][p] = ffma2(x3.y, wv.y, acc[3][p]);
                }
            }
            float b[8];
#pragma unroll
            for (int p = 0; p < 8; p++) b[p] = sm[OFF_B1 + wq*8 + p];
#pragma unroll
            for (int ri = 0; ri < 4; ri++) {
                int r = rg + 16*ri;
                float hv[8];
#pragma unroll
                for (int p = 0; p < 8; p++) {
                    float2 u = unpack2(acc[ri][p]);
                    hv[p] = fmaxf(u.x + u.y + b[p], 0.f);
                }
                *(float4*)&sm[OFF_H + r*HPAD + wq*8]     = make_float4(hv[0],hv[1],hv[2],hv[3]);
                *(float4*)&sm[OFF_H + r*HPAD + wq*8 + 4] = make_float4(hv[4],hv[5],hv[6],hv[7]);
            }
        }
        __syncthreads();

        // ---- GEMM2 + streamed spline over 4 chunks of 16 dims
        for (int chunk = 0; chunk < NCHUNK; chunk++) {
            const int d0 = chunk * DG;
            const int d  = d0 + dl;
            const int kmax   = kmax_of(d);
            const int chunkK = kmax_of(d0 + 15);
            const float* Wol = Wom + layer*DDIM*PPD*WIDTH;
            const float* bo  = boutg + (layer*DDIM + d)*PPD;

            float pr[4][8];
            float st_xraw[4], st_xi[4], st_invdx[4], st_yk[4], st_dyv[4], st_sk[4];
            int   st_k[4];

            // ===== phase 1: widths -> bin index, xi, invdx =====
            gemm2_pass<0, 8>(sm, Wol, bo, d0, dl, rg, chunkK, kmax, pr);
#pragma unroll
            for (int ri = 0; ri < 4; ri++) {
                float mw = pr[ri][0];
#pragma unroll
                for (int j = 1; j < 8; j++) mw = fmaxf(mw, pr[ri][j]);
                float ew[8]; float swv = 0.f;
#pragma unroll
                for (int j = 0; j < 8; j++) { ew[j] = __expf(pr[ri][j] - mw); swv += ew[j]; }
                float isw = __frcp_rn(swv);

                float xraw = sm[cur + (rg + 16*ri)*XPAD + d];
                float xc = fminf(fmaxf(xraw, -BI), BI);

                float xl = -BI;
                float xk = 0.f, xk1 = 1.f;
                int k = 7; bool found = false;
#pragma unroll
                for (int j = 0; j < 8; j++) {
                    float wj = (ew[j]*isw + CADJ) * C1;
                    float xr2 = xl + wj;
                    bool sel = (!found) && ((xc < xr2) || (j == 7));
                    if (sel) { k = j; xk = xl; xk1 = xr2; found = true; }
                    xl = xr2;
                }
                float invdx = __frcp_rn(xk1 - xk);
                st_xraw[ri] = xraw;
                st_invdx[ri] = invdx;
                st_xi[ri] = (xc - xk) * invdx;
                st_k[ri] = k;
            }

            // ===== phase 2: heights -> yk, dyv, sk =====
            gemm2_pass<8, 8>(sm, Wol, bo, d0, dl, rg, chunkK, kmax, pr);
#pragma unroll
            for (int ri = 0; ri < 4; ri++) {
                float mh = pr[ri][0];
#pragma unroll
                for (int j = 1; j < 8; j++) mh = fmaxf(mh, pr[ri][j]);
                float eh[8]; float shv = 0.f;
#pragma unroll
                for (int j = 0; j < 8; j++) { eh[j] = __expf(pr[ri][j] - mh); shv += eh[j]; }
                float ish = __frcp_rn(shv);

                const int k = st_k[ri];
                float yl = -BI;
                float yk = 0.f, yk1 = 1.f;
#pragma unroll
                for (int j = 0; j < 8; j++) {
                    float hj = (eh[j]*ish + CADJ) * C1;
                    float yr2 = yl + hj;
                    if (j == k) { yk = yl; yk1 = yr2; }
                    yl = yr2;
                }
                st_yk[ri] = yk;
                st_dyv[ri] = yk1 - yk;
                st_sk[ri] = st_dyv[ri] * st_invdx[ri];
            }

            // ===== phase 3: derivatives -> finish spline =====
            gemm2_pass<16, 7>(sm, Wol, bo, d0, dl, rg, chunkK, kmax, pr);
#pragma unroll
            for (int ri = 0; ri < 4; ri++) {
                const int k = st_k[ri];
                float dk = 1.f, dk1 = 1.f;
#pragma unroll
                for (int j = 0; j < 7; j++) {
                    float v = pr[ri][j];
                    float sp = (v > 15.f) ? v : log1pf(__expf(v));
                    float sdv = sp + 0.001f;
                    if (j == k - 1) dk  = sdv;
                    if (j == k)     dk1 = sdv;
                }
                float xi = st_xi[ri];
                float omx = 1.f - xi;
                float xiomx = xi * omx;
                float sk = st_sk[ri];
                float den = sk + (dk1 + dk - 2.f*sk) * xiomx;
                float invden = __frcp_rn(den);
                float nume = sk*xi*xi + dk*xiomx;
                float outv = st_yk[ri] + st_dyv[ri] * nume * invden;
                float ldn = dk1*xi*xi + 2.f*sk*xiomx + dk*omx*omx;
                float ld = 2.f*__logf(sk) + __logf(ldn) - 2.f*__logf(den);

                float xraw = st_xraw[ri];
                bool inside = (xraw > -BI) && (xraw < BI);
                float xo2 = inside ? outv : xraw;
                sm[nxt + (rg + 16*ri)*XPAD + (DDIM-1 - d)] = xo2;  // reversal fused
                ldacc[ri] += inside ? ld : 0.f;
            }
        }

        int t = cur; cur = nxt; nxt = t;
    }

    __syncthreads();

    // ---- outputs: [xo (B*64) | ldf (B) | yo (B*64) | ldg (B)]
    const int xbase  = flow ? (BATCH*DDIM + BATCH) : 0;
    const int ldbase = flow ? (2*BATCH*DDIM + BATCH) : (BATCH*DDIM);

    for (int i = tid; i < TB*DDIM; i += NTHREADS) {
        int rr = i >> 6, dd = i & 63;
        out[xbase + row0*DDIM + i] = sm[cur + rr*XPAD + dd];
    }

    // log-det reduction: 16 dim-class partials per row
    float* red = &sm[OFF_WS];
#pragma unroll
    for (int ri = 0; ri < 4; ri++)
        red[(rg + 16*ri)*16 + dl] = ldacc[ri];
    __syncthreads();
    if (tid < TB) {
        float s = 0.f;
#pragma unroll
        for (int j = 0; j < 16; j++) s += red[tid*16 + j];
        out[ldbase + row0 + tid] = s;
    }
}

// ---------------------------------------------------------------------------
extern "C" void kernel_launch(void* const* d_in, const int* in_sizes, int n_in,
                              void* d_out, int out_size)
{
    const float* x      = (const float*)d_in[0];
    const float* y      = (const float*)d_in[1];
    const float* f_W1   = (const float*)d_in[2];
    const float* f_b1   = (const float*)d_in[3];
    const float* f_Wout = (const float*)d_in[4];
    const float* f_bout = (const float*)d_in[5];
    const float* g_W1   = (const float*)d_in[6];
    const float* g_b1   = (const float*)d_in[7];
    const float* g_Wout = (const float*)d_in[8];
    const float* g_bout = (const float*)d_in[9];
    float* out = (float*)d_out;

    cudaFuncSetAttribute(maf_kernel, cudaFuncAttributeMaxDynamicSharedMemorySize, SMEM_BYTES);

    prep_kernel<<<1024, 256>>>(f_W1, f_Wout, g_W1, g_Wout, f_b1, g_b1);

    dim3 grid(BATCH/TB, 2);
    maf_kernel<<<grid, NTHREADS, SMEM_BYTES>>>(x, y, f_bout, g_bout, out);
}